// round 6
// baseline (speedup 1.0000x reference)
#include <cuda_runtime.h>
#include <cuda_bf16.h>

// HSMNet cost-volume + channel-sum + softmax disparity regression, fused.
// B=4, C=32, H=80, W=160, D=24. Output [B,H,W] f32.
//
// R6: 8-way disparity split to double warp count (6400 warps, occ ceiling 67%)
// while keeping vectorized LDS. Thread = (w-pair, dg), dg in [0,8): 2 pixels x
// 3 disparities; per channel 1 ref LDS.64 + 3 tgt LDS.64 feed 12 |diff| adds.
// dg = tid&7 -> in-warp softmax merge via 3x shfl.xor. Half-row CTAs:
// 640 CTAs x 320 threads. All smem vector loads conflict-free (broadcast-only
// collisions, verified by bank arithmetic).

#define Bc 4
#define Cc 32
#define Hc 80
#define Wc 160
#define Dc 24
#define DG 8
#define DPG 3
#define HALF 80              // pixels per CTA
#define NWB (HALF / 2)       // 40 w-pairs
#define NT (NWB * DG)        // 320 threads
#define TROW 112             // tgt cols staged: [w_start-32, w_start+80)
#define RROW 80              // ref cols staged: [w_start, w_start+80)

__global__ __launch_bounds__(NT)
void hsm_dispreg_kernel(const float* __restrict__ ref,
                        const float* __restrict__ tgt,
                        float* __restrict__ out)
{
    __shared__ __align__(16) float st[Cc * TROW];   // tgt window
    __shared__ __align__(16) float sr[Cc * RROW];   // ref half-row

    const int half = blockIdx.x;             // 0,1
    const int h    = blockIdx.y;
    const int b    = blockIdx.z;
    const int tid  = threadIdx.x;
    const int dg   = tid & 7;                // 0..7 (in-lane)
    const int wb   = tid >> 3;               // 0..39
    const int w_start = half * HALF;
    const int w0   = w_start + wb * 2;
    const int d0   = dg * DPG;
    const int e    = dg & 1;                 // parity fix for even window base

    // ---- stage tgt window [w_start-32, w_start+80) x 32 channels ----
    {
        const int rowbase = (b * Cc * Hc + h) * Wc;
#pragma unroll
        for (int k = 0; k < (Cc * TROW + NT - 1) / NT; ++k) {
            const int idx = tid + k * NT;
            if (idx < Cc * TROW) {
                const int c = idx / TROW;
                const int l = idx - c * TROW;
                const int gcol = w_start - 32 + l;
                st[idx] = ((unsigned)gcol < (unsigned)Wc)
                            ? tgt[rowbase + c * Hc * Wc + gcol] : 0.0f;
            }
        }
#pragma unroll
        for (int k = 0; k < (Cc * RROW) / NT; ++k) {
            const int idx = tid + k * NT;
            const int c = idx / RROW;
            const int l = idx - c * RROW;
            sr[idx] = ref[rowbase + c * Hc * Wc + w_start + l];
        }
    }
    __syncthreads();

    // ---- accumulate 2 pixels x 3 disparities ----
    float cost0[DPG] = {0.f, 0.f, 0.f};
    float cost1[DPG] = {0.f, 0.f, 0.f};

    // window start (global float idx) = w0 - d0 - e - 2  (even);
    // local col = that - (w_start - 32) = 2*wb + 30 - d0 - e  (even, >= 8)
    const float* tp = &st[2 * wb + 30 - d0 - e];
    const float* rp = &sr[2 * wb];

    // slot of tgt[w0+p-(d0+j)] within window = e + 2 + p - j, in [e, e+3] ⊆ [0,4]
#pragma unroll 4
    for (int c = 0; c < Cc; ++c) {
        const float2 r = *(const float2*)(rp + c * RROW);
        float t[6];
#pragma unroll
        for (int k = 0; k < 3; ++k) {
            const float2 tt = *(const float2*)(tp + c * TROW + 2 * k);
            t[2 * k]     = tt.x;
            t[2 * k + 1] = tt.y;
        }
#pragma unroll
        for (int j = 0; j < DPG; ++j) {
            if (w0 >= d0 + j)     cost0[j] += fabsf(r.x - t[e + 2 - j]);
            if (w0 + 1 >= d0 + j) cost1[j] += fabsf(r.y - t[e + 3 - j]);
        }
    }

    // ---- exact two-pass softmax + expectation, merged across 8 dg lanes ----
    float m0 = fmaxf(fmaxf(cost0[0], cost0[1]), cost0[2]);
    float m1 = fmaxf(fmaxf(cost1[0], cost1[1]), cost1[2]);
    m0 = fmaxf(m0, __shfl_xor_sync(0xffffffffu, m0, 1));
    m0 = fmaxf(m0, __shfl_xor_sync(0xffffffffu, m0, 2));
    m0 = fmaxf(m0, __shfl_xor_sync(0xffffffffu, m0, 4));
    m1 = fmaxf(m1, __shfl_xor_sync(0xffffffffu, m1, 1));
    m1 = fmaxf(m1, __shfl_xor_sync(0xffffffffu, m1, 2));
    m1 = fmaxf(m1, __shfl_xor_sync(0xffffffffu, m1, 4));

    float s0 = 0.f, n0 = 0.f, s1 = 0.f, n1 = 0.f;
#pragma unroll
    for (int j = 0; j < DPG; ++j) {
        const float e0 = __expf(cost0[j] - m0);   // invalid entries carry cost 0 (as reference)
        const float e1 = __expf(cost1[j] - m1);
        s0 += e0;  n0 += (float)(d0 + j) * e0;
        s1 += e1;  n1 += (float)(d0 + j) * e1;
    }
    s0 += __shfl_xor_sync(0xffffffffu, s0, 1);
    s0 += __shfl_xor_sync(0xffffffffu, s0, 2);
    s0 += __shfl_xor_sync(0xffffffffu, s0, 4);
    n0 += __shfl_xor_sync(0xffffffffu, n0, 1);
    n0 += __shfl_xor_sync(0xffffffffu, n0, 2);
    n0 += __shfl_xor_sync(0xffffffffu, n0, 4);
    s1 += __shfl_xor_sync(0xffffffffu, s1, 1);
    s1 += __shfl_xor_sync(0xffffffffu, s1, 2);
    s1 += __shfl_xor_sync(0xffffffffu, s1, 4);
    n1 += __shfl_xor_sync(0xffffffffu, n1, 1);
    n1 += __shfl_xor_sync(0xffffffffu, n1, 2);
    n1 += __shfl_xor_sync(0xffffffffu, n1, 4);

    if (dg == 0) {
        float2 o;
        o.x = n0 / s0;
        o.y = n1 / s1;
        *(float2*)&out[(b * Hc + h) * Wc + w0] = o;
    }
}

extern "C" void kernel_launch(void* const* d_in, const int* in_sizes, int n_in,
                              void* d_out, int out_size)
{
    const float* ref = (const float*)d_in[0];
    const float* tgt = (const float*)d_in[1];
    float* out = (float*)d_out;

    dim3 grid(2, Hc, Bc);   // 640 CTAs x 320 threads = 204800 threads
    hsm_dispreg_kernel<<<grid, NT>>>(ref, tgt, out);
}

// round 8
// speedup vs baseline: 2.0785x; 2.0785x over previous
#include <cuda_runtime.h>
#include <cuda_bf16.h>

// HSMNet cost-volume + channel-sum + softmax disparity regression, fused.
// B=4, C=32, H=80, W=160, D=24. Output [B,H,W] f32.
//
// R8: R7 with the odd-parity window offset corrected (+33 -> +31).
// 8-way disparity split (204800 threads, 6400 warps), all inner-loop indices
// compile-time. tgt staged twice (stE even-aligned, stO shifted one float,
// 16-float skew); thread picks its array via one hoisted pointer select.
// Inner loop per channel: 1 ref LDS.64 + 2 tgt LDS.64 -> 6 unpredicated adds.
// Validity (d > w) fixed post-loop. Softmax merged across 8 dg lanes via
// shfl.xor 4/8/16. 640 CTAs x 320 threads, all co-resident.

#define Bc 4
#define Cc 32
#define Hc 80
#define Wc 160
#define Dc 24
#define HALF 80
#define NT 320
#define TROW 114
#define RROW 80
#define OFF_E 0
#define OFF_O (Cc * TROW + 16)            // +16-float skew vs stE
#define OFF_R (OFF_O + Cc * TROW)
#define SMEMF (OFF_R + Cc * RROW)         // 9872 floats = 39488 B

__global__ __launch_bounds__(NT, 5)
void hsm_dispreg_kernel(const float* __restrict__ ref,
                        const float* __restrict__ tgt,
                        float* __restrict__ out)
{
    __shared__ __align__(16) float sm[SMEMF];

    const int half = blockIdx.x;              // 0,1
    const int h    = blockIdx.y;
    const int b    = blockIdx.z;
    const int tid  = threadIdx.x;

    const int w_start = half * HALF;
    const int rowbase = (b * Cc * Hc + h) * Wc;
    const int HW = Hc * Wc;

    // ---- stage tgt twice: stE[c][l] = tgt[g0+l], stO[c][l] = tgt[g0+1+l] ----
    const int g0 = w_start - 34;              // even for both halves
#pragma unroll
    for (int k = 0; k < (Cc * TROW + NT - 1) / NT; ++k) {
        const int idx = tid + k * NT;
        if (idx < Cc * TROW) {
            const int c = idx / TROW;
            const int l = idx - c * TROW;
            const int gE = g0 + l;
            const int gO = g0 + 1 + l;
            sm[OFF_E + idx] = ((unsigned)gE < (unsigned)Wc) ? tgt[rowbase + c * HW + gE] : 0.f;
            sm[OFF_O + idx] = ((unsigned)gO < (unsigned)Wc) ? tgt[rowbase + c * HW + gO] : 0.f;
        }
    }
    // ---- stage ref half-row ----
#pragma unroll
    for (int k = 0; k < (Cc * RROW) / NT; ++k) {
        const int idx = tid + k * NT;
        const int c = idx / RROW;
        const int l = idx - c * RROW;
        sm[OFF_R + idx] = ref[rowbase + c * HW + w_start + l];
    }
    __syncthreads();

    // lane map: dg = (tid>>2)&7 (in-warp), wb = warp*4 + (tid&3)
    const int dg  = (tid >> 2) & 7;
    const int wb  = ((tid >> 5) << 2) + (tid & 3);   // 0..39
    const int w0  = w_start + 2 * wb;
    const int d0  = 3 * dg;

    // t[i] = tgt[(w0 - d0 - 2) + i]:
    //   even d0: l = (w0-d0-2) - g0      = 2*wb - d0 + 32
    //   odd  d0: l = (w0-d0-2) - (g0+1)  = 2*wb - d0 + 31
    const float* tbase = (d0 & 1) ? (sm + OFF_O + (2 * wb - d0 + 31))
                                  : (sm + OFF_E + (2 * wb - d0 + 32));
    const float* rbase = sm + OFF_R + 2 * wb;

    float c00 = 0.f, c01 = 0.f, c02 = 0.f;   // pixel w0,   d = d0+0,1,2
    float c10 = 0.f, c11 = 0.f, c12 = 0.f;   // pixel w0+1, d = d0+0,1,2

#pragma unroll
    for (int c = 0; c < Cc; ++c) {
        const float2 r  = *(const float2*)(rbase + c * RROW);
        const float2 tA = *(const float2*)(tbase + c * TROW);      // t0,t1
        const float2 tB = *(const float2*)(tbase + c * TROW + 2);  // t2,t3
        // item(p,j): slot = 2 + p - j
        c00 += fabsf(r.x - tB.x);   // p0 j0 -> t2 = tgt[w0-d0]
        c01 += fabsf(r.x - tA.y);   // p0 j1 -> t1 = tgt[w0-d0-1]
        c02 += fabsf(r.x - tA.x);   // p0 j2 -> t0 = tgt[w0-d0-2]
        c10 += fabsf(r.y - tB.y);   // p1 j0 -> t3
        c11 += fabsf(r.y - tB.x);   // p1 j1 -> t2
        c12 += fabsf(r.y - tA.y);   // p1 j2 -> t1
    }

    // validity fix: cost = 0 where d > w (reference zeroes invalid entries)
    if (w0 <  d0    ) c00 = 0.f;
    if (w0 <  d0 + 1) c01 = 0.f;
    if (w0 <  d0 + 2) c02 = 0.f;
    if (w0 + 1 < d0    ) c10 = 0.f;
    if (w0 + 1 < d0 + 1) c11 = 0.f;
    if (w0 + 1 < d0 + 2) c12 = 0.f;

    // ---- exact two-pass softmax + expectation across the 8 dg lanes ----
    float m0 = fmaxf(fmaxf(c00, c01), c02);
    float m1 = fmaxf(fmaxf(c10, c11), c12);
    m0 = fmaxf(m0, __shfl_xor_sync(0xffffffffu, m0, 4));
    m0 = fmaxf(m0, __shfl_xor_sync(0xffffffffu, m0, 8));
    m0 = fmaxf(m0, __shfl_xor_sync(0xffffffffu, m0, 16));
    m1 = fmaxf(m1, __shfl_xor_sync(0xffffffffu, m1, 4));
    m1 = fmaxf(m1, __shfl_xor_sync(0xffffffffu, m1, 8));
    m1 = fmaxf(m1, __shfl_xor_sync(0xffffffffu, m1, 16));

    const float e00 = __expf(c00 - m0), e01 = __expf(c01 - m0), e02 = __expf(c02 - m0);
    const float e10 = __expf(c10 - m1), e11 = __expf(c11 - m1), e12 = __expf(c12 - m1);
    const float fd0 = (float)d0;
    float s0 = e00 + e01 + e02;
    float n0 = fd0 * e00 + (fd0 + 1.f) * e01 + (fd0 + 2.f) * e02;
    float s1 = e10 + e11 + e12;
    float n1 = fd0 * e10 + (fd0 + 1.f) * e11 + (fd0 + 2.f) * e12;

    s0 += __shfl_xor_sync(0xffffffffu, s0, 4);
    s0 += __shfl_xor_sync(0xffffffffu, s0, 8);
    s0 += __shfl_xor_sync(0xffffffffu, s0, 16);
    n0 += __shfl_xor_sync(0xffffffffu, n0, 4);
    n0 += __shfl_xor_sync(0xffffffffu, n0, 8);
    n0 += __shfl_xor_sync(0xffffffffu, n0, 16);
    s1 += __shfl_xor_sync(0xffffffffu, s1, 4);
    s1 += __shfl_xor_sync(0xffffffffu, s1, 8);
    s1 += __shfl_xor_sync(0xffffffffu, s1, 16);
    n1 += __shfl_xor_sync(0xffffffffu, n1, 4);
    n1 += __shfl_xor_sync(0xffffffffu, n1, 8);
    n1 += __shfl_xor_sync(0xffffffffu, n1, 16);

    if (dg == 0) {
        float2 o;
        o.x = n0 / s0;
        o.y = n1 / s1;
        *(float2*)&out[(b * Hc + h) * Wc + w0] = o;
    }
}

extern "C" void kernel_launch(void* const* d_in, const int* in_sizes, int n_in,
                              void* d_out, int out_size)
{
    const float* ref = (const float*)d_in[0];
    const float* tgt = (const float*)d_in[1];
    float* out = (float*)d_out;

    dim3 grid(2, Hc, Bc);   // 640 CTAs x 320 threads
    hsm_dispreg_kernel<<<grid, NT>>>(ref, tgt, out);
}

// round 9
// speedup vs baseline: 2.7870x; 1.3409x over previous
#include <cuda_runtime.h>
#include <cuda_bf16.h>

// HSMNet cost-volume + channel-sum + softmax disparity regression, fused.
// B=4, C=32, H=80, W=160, D=24. Output [B,H,W] f32.
//
// R9: thread = (w-pair, dg in [0,4), cg in [0,2)): 2 px x 6 disp x 16 ch.
// 204800 threads / 6400 warps (occ ceiling 67%) with NO extra LDS traffic:
// each channel's loads happen exactly once per (wpair,dg). Lane map
// cg*16 + dg*4 + wbL keeps every LDS.64 16-lane phase cg-uniform ->
// tgt offsets 2*wbL - 6*dg span 26 banks, collisions are exact-address
// broadcasts -> conflict-free. Merge: shfl.xor 16 (cg cost sum), 4/8 (dg
// softmax). Quarter-row CTAs: 1280 CTAs x 160 thr (9-vs-8/SM, 1.04x tail).

#define Bc 4
#define Cc 32
#define Hc 80
#define Wc 160
#define Dc 24
#define QW 40                 // pixels per CTA (quarter row)
#define NWB 20                // w-pairs per CTA
#define NT 160                // 20 wpairs * 8 (dg*cg)
#define TROW 64               // tgt cols staged: [w_start-24, w_start+40)
#define RROW 40               // ref cols staged: [w_start, w_start+40)
#define CPT 16                // channels per thread

__global__ __launch_bounds__(NT, 9)
void hsm_dispreg_kernel(const float* __restrict__ ref,
                        const float* __restrict__ tgt,
                        float* __restrict__ out)
{
    __shared__ __align__(16) float st[Cc * TROW];   // 2048 floats
    __shared__ __align__(16) float sr[Cc * RROW];   // 1280 floats

    const int q   = blockIdx.x;              // 0..3
    const int h   = blockIdx.y;
    const int b   = blockIdx.z;
    const int tid = threadIdx.x;

    const int w_start = q * QW;
    const int rowbase = (b * Cc * Hc + h) * Wc;
    const int HW = Hc * Wc;
    const int g0 = w_start - 24;

    // ---- stage tgt window [w_start-24, w_start+40) x 32 ch (idx = c*64+l) ----
#pragma unroll
    for (int k = 0; k < (Cc * TROW) / NT; ++k) {       // 2048/160 = 12.8 -> 13
        const int idx = tid + k * NT;
        const int c = idx >> 6;
        const int l = idx & 63;
        const int g = g0 + l;
        st[idx] = ((unsigned)g < (unsigned)Wc) ? tgt[rowbase + c * HW + g] : 0.f;
    }
    {   // remainder
        const int idx = tid + ((Cc * TROW) / NT) * NT;
        if (idx < Cc * TROW) {
            const int c = idx >> 6;
            const int l = idx & 63;
            const int g = g0 + l;
            st[idx] = ((unsigned)g < (unsigned)Wc) ? tgt[rowbase + c * HW + g] : 0.f;
        }
    }
    // ---- stage ref quarter-row ----
#pragma unroll
    for (int k = 0; k < (Cc * RROW) / NT; ++k) {       // 1280/160 = 8
        const int idx = tid + k * NT;
        const int c = idx / RROW;
        const int l = idx - c * RROW;
        sr[idx] = ref[rowbase + c * HW + w_start + l];
    }
    __syncthreads();

    // lane bits: wbL = lane&3, dg = (lane>>2)&3, cg = (lane>>4)&1
    const int lane = tid & 31;
    const int warp = tid >> 5;               // 0..4
    const int wbq  = warp * 4 + (lane & 3);  // 0..19
    const int dg   = (lane >> 2) & 3;
    const int cg   = lane >> 4;
    const int w0   = w_start + 2 * wbq;
    const int d0   = 6 * dg;

    // window t[i] = tgt[(w0 - d0 - 6) + i], i in [0,8); local base even
    const float* tp = st + (2 * wbq - d0 + 18);        // + c*TROW
    const float* rp = sr + 2 * wbq;                    // + c*RROW
    const int c0 = cg * CPT;

    float c00 = 0.f, c01 = 0.f, c02 = 0.f, c03 = 0.f, c04 = 0.f, c05 = 0.f;
    float c10 = 0.f, c11 = 0.f, c12 = 0.f, c13 = 0.f, c14 = 0.f, c15 = 0.f;

#pragma unroll
    for (int k = 0; k < CPT; ++k) {
        const int c = c0 + k;
        const float2 r  = *(const float2*)(rp + c * RROW);
        const float2 tA = *(const float2*)(tp + c * TROW);      // t0,t1
        const float2 tB = *(const float2*)(tp + c * TROW + 2);  // t2,t3
        const float2 tC = *(const float2*)(tp + c * TROW + 4);  // t4,t5
        const float2 tD = *(const float2*)(tp + c * TROW + 6);  // t6,t7
        // item(p,j): slot = 6 + p - j ; t[s] = tgt[w0-d0-6+s]
        c00 += fabsf(r.x - tD.x);   // p0 j0 -> t6
        c01 += fabsf(r.x - tC.y);   // p0 j1 -> t5
        c02 += fabsf(r.x - tC.x);   // p0 j2 -> t4
        c03 += fabsf(r.x - tB.y);   // p0 j3 -> t3
        c04 += fabsf(r.x - tB.x);   // p0 j4 -> t2
        c05 += fabsf(r.x - tA.y);   // p0 j5 -> t1
        c10 += fabsf(r.y - tD.y);   // p1 j0 -> t7
        c11 += fabsf(r.y - tD.x);   // p1 j1 -> t6
        c12 += fabsf(r.y - tC.y);   // p1 j2 -> t5
        c13 += fabsf(r.y - tC.x);   // p1 j3 -> t4
        c14 += fabsf(r.y - tB.y);   // p1 j4 -> t3
        c15 += fabsf(r.y - tB.x);   // p1 j5 -> t2
    }

    // ---- sum partial costs across cg (lanes xor 16) ----
    c00 += __shfl_xor_sync(0xffffffffu, c00, 16);
    c01 += __shfl_xor_sync(0xffffffffu, c01, 16);
    c02 += __shfl_xor_sync(0xffffffffu, c02, 16);
    c03 += __shfl_xor_sync(0xffffffffu, c03, 16);
    c04 += __shfl_xor_sync(0xffffffffu, c04, 16);
    c05 += __shfl_xor_sync(0xffffffffu, c05, 16);
    c10 += __shfl_xor_sync(0xffffffffu, c10, 16);
    c11 += __shfl_xor_sync(0xffffffffu, c11, 16);
    c12 += __shfl_xor_sync(0xffffffffu, c12, 16);
    c13 += __shfl_xor_sync(0xffffffffu, c13, 16);
    c14 += __shfl_xor_sync(0xffffffffu, c14, 16);
    c15 += __shfl_xor_sync(0xffffffffu, c15, 16);

    // validity: cost = 0 where d > w (reference zeroes invalid entries)
    if (w0 < d0    ) c00 = 0.f;
    if (w0 < d0 + 1) c01 = 0.f;
    if (w0 < d0 + 2) c02 = 0.f;
    if (w0 < d0 + 3) c03 = 0.f;
    if (w0 < d0 + 4) c04 = 0.f;
    if (w0 < d0 + 5) c05 = 0.f;
    if (w0 + 1 < d0    ) c10 = 0.f;
    if (w0 + 1 < d0 + 1) c11 = 0.f;
    if (w0 + 1 < d0 + 2) c12 = 0.f;
    if (w0 + 1 < d0 + 3) c13 = 0.f;
    if (w0 + 1 < d0 + 4) c14 = 0.f;
    if (w0 + 1 < d0 + 5) c15 = 0.f;

    // ---- exact two-pass softmax + expectation across the 4 dg lanes ----
    float m0 = fmaxf(fmaxf(fmaxf(c00, c01), fmaxf(c02, c03)), fmaxf(c04, c05));
    float m1 = fmaxf(fmaxf(fmaxf(c10, c11), fmaxf(c12, c13)), fmaxf(c14, c15));
    m0 = fmaxf(m0, __shfl_xor_sync(0xffffffffu, m0, 4));
    m0 = fmaxf(m0, __shfl_xor_sync(0xffffffffu, m0, 8));
    m1 = fmaxf(m1, __shfl_xor_sync(0xffffffffu, m1, 4));
    m1 = fmaxf(m1, __shfl_xor_sync(0xffffffffu, m1, 8));

    const float e00 = __expf(c00 - m0), e01 = __expf(c01 - m0), e02 = __expf(c02 - m0);
    const float e03 = __expf(c03 - m0), e04 = __expf(c04 - m0), e05 = __expf(c05 - m0);
    const float e10 = __expf(c10 - m1), e11 = __expf(c11 - m1), e12 = __expf(c12 - m1);
    const float e13 = __expf(c13 - m1), e14 = __expf(c14 - m1), e15 = __expf(c15 - m1);

    const float fd = (float)d0;
    float s0 = ((e00 + e01) + (e02 + e03)) + (e04 + e05);
    float n0 = fd * e00 + (fd + 1.f) * e01 + (fd + 2.f) * e02
             + (fd + 3.f) * e03 + (fd + 4.f) * e04 + (fd + 5.f) * e05;
    float s1 = ((e10 + e11) + (e12 + e13)) + (e14 + e15);
    float n1 = fd * e10 + (fd + 1.f) * e11 + (fd + 2.f) * e12
             + (fd + 3.f) * e13 + (fd + 4.f) * e14 + (fd + 5.f) * e15;

    s0 += __shfl_xor_sync(0xffffffffu, s0, 4);
    s0 += __shfl_xor_sync(0xffffffffu, s0, 8);
    n0 += __shfl_xor_sync(0xffffffffu, n0, 4);
    n0 += __shfl_xor_sync(0xffffffffu, n0, 8);
    s1 += __shfl_xor_sync(0xffffffffu, s1, 4);
    s1 += __shfl_xor_sync(0xffffffffu, s1, 8);
    n1 += __shfl_xor_sync(0xffffffffu, n1, 4);
    n1 += __shfl_xor_sync(0xffffffffu, n1, 8);

    if (dg == 0 && cg == 0) {
        float2 o;
        o.x = n0 / s0;
        o.y = n1 / s1;
        *(float2*)&out[(b * Hc + h) * Wc + w0] = o;
    }
}

extern "C" void kernel_launch(void* const* d_in, const int* in_sizes, int n_in,
                              void* d_out, int out_size)
{
    const float* ref = (const float*)d_in[0];
    const float* tgt = (const float*)d_in[1];
    float* out = (float*)d_out;

    dim3 grid(4, Hc, Bc);   // 1280 CTAs x 160 threads = 204800 threads
    hsm_dispreg_kernel<<<grid, NT>>>(ref, tgt, out);
}